// round 1
// baseline (speedup 1.0000x reference)
#include <cuda_runtime.h>
#include <math.h>

// Problem constants
#define Bq 8
#define Tq 1024
#define Cq 1024
#define Hq 16
#define Dq 64
#define Mq (Bq * Tq)          // 8192 rows
#define BHq (Bq * Hq)         // 128

// ---------------------------------------------------------------------------
// Scratch (device globals; no dynamic allocation allowed)
// ---------------------------------------------------------------------------
__device__ float g_q[(size_t)BHq * Tq * Dq];     // [B,H,T,D]  32 MB
__device__ float g_k[(size_t)BHq * Tq * Dq];     // [B,H,T,D]  32 MB
__device__ float g_v[(size_t)BHq * Tq * Dq];     // [B,H,T,D]  32 MB
__device__ float g_ctx[(size_t)Mq * Cq];         // [B,T,C]    32 MB
__device__ float g_wq[(size_t)Cq * Cq];          // packed [C, H*D]
__device__ float g_wk[(size_t)Cq * Cq];
__device__ float g_wv[(size_t)Cq * Cq];
__device__ float g_wpT[(size_t)Cq * Cq];         // Wproj^T: [K=C, N=C]

// ---------------------------------------------------------------------------
// Weight repack: Wq/Wk/Wv [H,C,D] -> [C, H*D]
// ---------------------------------------------------------------------------
__global__ void repack_qkv_kernel(const float* __restrict__ W, float* __restrict__ P) {
    int i = blockIdx.x * blockDim.x + threadIdx.x;   // over C * (H*D) = 1M
    int c = i >> 10;
    int n = i & 1023;
    int h = n >> 6;
    int d = n & 63;
    P[i] = W[((size_t)h * Cq + c) * Dq + d];
}

// Wproj [N,K] row-major -> WprojT [K,N]
__global__ void repack_projT_kernel(const float* __restrict__ W, float* __restrict__ P) {
    int i = blockIdx.x * blockDim.x + threadIdx.x;   // over C*C
    int k = i >> 10;
    int n = i & 1023;
    P[i] = W[(size_t)n * Cq + k];
}

// ---------------------------------------------------------------------------
// SGEMM 128x128x16, 256 threads, 8x8 per thread.
// mode 0: Cout[m*N+n] = acc + bias[n]   (row-major, bias optional)
// mode 1: scatter to [B,H,T,D]: m=(b,t), n=(h,d)
// ---------------------------------------------------------------------------
__global__ __launch_bounds__(256) void sgemm128(
    const float* __restrict__ A, const float* __restrict__ Bm,
    float* __restrict__ Cout, int K, int N, int mode,
    const float* __restrict__ bias)
{
    __shared__ float As[16][132];   // padded
    __shared__ float Bs[16][128];

    const int tid  = threadIdx.x;
    const int row0 = blockIdx.y * 128;
    const int col0 = blockIdx.x * 128;
    const int tr   = (tid >> 4) << 3;   // 0..120
    const int tc   = (tid & 15) << 3;

    float acc[8][8];
#pragma unroll
    for (int i = 0; i < 8; i++)
#pragma unroll
        for (int j = 0; j < 8; j++) acc[i][j] = 0.f;

    for (int k0 = 0; k0 < K; k0 += 16) {
#pragma unroll
        for (int l = 0; l < 2; l++) {
            int f  = tid + l * 256;
            // A tile: 128 rows x 16 cols (4 float4 per row)
            int ra = f >> 2, ca = (f & 3) << 2;
            float4 va = *(const float4*)(A + (size_t)(row0 + ra) * K + k0 + ca);
            As[ca + 0][ra] = va.x;
            As[ca + 1][ra] = va.y;
            As[ca + 2][ra] = va.z;
            As[ca + 3][ra] = va.w;
            // B tile: 16 rows x 128 cols
            int rb = f >> 5, cb = (f & 31) << 2;
            float4 vb = *(const float4*)(Bm + (size_t)(k0 + rb) * N + col0 + cb);
            *(float4*)(&Bs[rb][cb]) = vb;
        }
        __syncthreads();

#pragma unroll
        for (int kk = 0; kk < 16; kk++) {
            float rm[8], rn[8];
#pragma unroll
            for (int i = 0; i < 8; i++) rm[i] = As[kk][tr + i];
#pragma unroll
            for (int j = 0; j < 8; j++) rn[j] = Bs[kk][tc + j];
#pragma unroll
            for (int i = 0; i < 8; i++)
#pragma unroll
                for (int j = 0; j < 8; j++)
                    acc[i][j] = fmaf(rm[i], rn[j], acc[i][j]);
        }
        __syncthreads();
    }

    if (mode == 0) {
#pragma unroll
        for (int i = 0; i < 8; i++) {
            int m = row0 + tr + i;
#pragma unroll
            for (int j = 0; j < 8; j++) {
                int n = col0 + tc + j;
                float v = acc[i][j];
                if (bias) v += bias[n];
                Cout[(size_t)m * N + n] = v;
            }
        }
    } else {
#pragma unroll
        for (int i = 0; i < 8; i++) {
            int m = row0 + tr + i;
            int b = m >> 10, t = m & 1023;
#pragma unroll
            for (int j = 0; j < 8; j++) {
                int n = col0 + tc + j;
                int h = n >> 6, d = n & 63;
                Cout[((size_t)(b * Hq + h) * Tq + t) * Dq + d] = acc[i][j];
            }
        }
    }
}

// ---------------------------------------------------------------------------
// Scores: S[t,s] = q[t]·k[s] / 8 for lower-triangular 64x64 tiles.
// grid (sTile=16, tTile=16, bh=128). Blocks with sTile>tTile skipped.
// ---------------------------------------------------------------------------
__global__ __launch_bounds__(256) void scores_kernel(float* __restrict__ wei) {
    int sT = blockIdx.x, tT = blockIdx.y, bh = blockIdx.z;
    if (sT > tT) return;

    __shared__ float Qs[64][65];   // [d][t]
    __shared__ float Ks[64][65];   // [d][s]
    int tid = threadIdx.x;

    const float* qb = g_q + (size_t)bh * Tq * Dq + (size_t)tT * 64 * Dq;
    const float* kb = g_k + (size_t)bh * Tq * Dq + (size_t)sT * 64 * Dq;

#pragma unroll
    for (int l = 0; l < 4; l++) {
        int f = tid + l * 256;
        int r = f >> 4, c4 = (f & 15) << 2;
        float4 vq = *(const float4*)(qb + r * Dq + c4);
        Qs[c4 + 0][r] = vq.x; Qs[c4 + 1][r] = vq.y;
        Qs[c4 + 2][r] = vq.z; Qs[c4 + 3][r] = vq.w;
        float4 vk = *(const float4*)(kb + r * Dq + c4);
        Ks[c4 + 0][r] = vk.x; Ks[c4 + 1][r] = vk.y;
        Ks[c4 + 2][r] = vk.z; Ks[c4 + 3][r] = vk.w;
    }
    __syncthreads();

    int tr = (tid >> 4) << 2;   // t within tile
    int tc = (tid & 15) << 2;   // s within tile
    float acc[4][4];
#pragma unroll
    for (int i = 0; i < 4; i++)
#pragma unroll
        for (int j = 0; j < 4; j++) acc[i][j] = 0.f;

#pragma unroll
    for (int kk = 0; kk < 64; kk++) {
        float rq[4], rk[4];
#pragma unroll
        for (int i = 0; i < 4; i++) rq[i] = Qs[kk][tr + i];
#pragma unroll
        for (int j = 0; j < 4; j++) rk[j] = Ks[kk][tc + j];
#pragma unroll
        for (int i = 0; i < 4; i++)
#pragma unroll
            for (int j = 0; j < 4; j++)
                acc[i][j] = fmaf(rq[i], rk[j], acc[i][j]);
    }

    float* w = wei + (size_t)bh * Tq * Tq + (size_t)(tT * 64) * Tq + sT * 64;
#pragma unroll
    for (int i = 0; i < 4; i++)
#pragma unroll
        for (int j = 0; j < 4; j++)
            w[(size_t)(tr + i) * Tq + tc + j] = acc[i][j] * 0.125f;
}

// ---------------------------------------------------------------------------
// Row softmax with causal mask, in place. One block per row (B*H*T rows).
// Writes exact 0 for s > t.
// ---------------------------------------------------------------------------
__global__ __launch_bounds__(256) void softmax_kernel(float* __restrict__ wei) {
    int row = blockIdx.x;
    int t   = row & (Tq - 1);
    float* p = wei + (size_t)row * Tq;
    int tid  = threadIdx.x;

    float vals[4];
    float mx = -INFINITY;
#pragma unroll
    for (int u = 0; u < 4; u++) {
        int s = tid + u * 256;
        vals[u] = (s <= t) ? p[s] : -INFINITY;
        mx = fmaxf(mx, vals[u]);
    }
#pragma unroll
    for (int o = 16; o; o >>= 1) mx = fmaxf(mx, __shfl_xor_sync(0xffffffffu, mx, o));

    __shared__ float red[8];
    if ((tid & 31) == 0) red[tid >> 5] = mx;
    __syncthreads();
    if (tid < 32) {
        float m2 = (tid < 8) ? red[tid] : -INFINITY;
#pragma unroll
        for (int o = 4; o; o >>= 1) m2 = fmaxf(m2, __shfl_xor_sync(0xffffffffu, m2, o));
        if (tid == 0) red[0] = m2;
    }
    __syncthreads();
    mx = red[0];
    __syncthreads();

    float sum = 0.f;
#pragma unroll
    for (int u = 0; u < 4; u++) {
        vals[u] = expf(vals[u] - mx);   // exp(-inf)=0 for masked lanes
        sum += vals[u];
    }
#pragma unroll
    for (int o = 16; o; o >>= 1) sum += __shfl_xor_sync(0xffffffffu, sum, o);
    if ((tid & 31) == 0) red[tid >> 5] = sum;
    __syncthreads();
    if (tid < 32) {
        float s2 = (tid < 8) ? red[tid] : 0.f;
#pragma unroll
        for (int o = 4; o; o >>= 1) s2 += __shfl_xor_sync(0xffffffffu, s2, o);
        if (tid == 0) red[0] = s2;
    }
    __syncthreads();
    float inv = 1.0f / red[0];

#pragma unroll
    for (int u = 0; u < 4; u++) {
        int s = tid + u * 256;
        p[s] = vals[u] * inv;
    }
}

// ---------------------------------------------------------------------------
// ctx = P @ V per (b,h). Block = 64 t-rows x 64 d-cols; loops over s-tiles
// up to the diagonal. Output written in [B,T,C] layout for the out-proj GEMM.
// ---------------------------------------------------------------------------
__global__ __launch_bounds__(256) void ctx_kernel(const float* __restrict__ wei) {
    int tT = blockIdx.x, bh = blockIdx.y;
    int b = bh >> 4, h = bh & 15;

    __shared__ float Ps[64][65];   // [s][t]
    __shared__ float Vs[64][64];   // [s][d]
    int tid = threadIdx.x;
    int tr = (tid >> 4) << 2;      // t within tile
    int tc = (tid & 15) << 2;      // d within tile

    float acc[4][4];
#pragma unroll
    for (int i = 0; i < 4; i++)
#pragma unroll
        for (int j = 0; j < 4; j++) acc[i][j] = 0.f;

    const float* wb = wei + (size_t)bh * Tq * Tq + (size_t)(tT * 64) * Tq;
    const float* vb = g_v + (size_t)bh * Tq * Dq;

    for (int sT = 0; sT <= tT; sT++) {
#pragma unroll
        for (int l = 0; l < 4; l++) {
            int f = tid + l * 256;
            int r = f >> 4, c4 = (f & 15) << 2;
            float4 vp = *(const float4*)(wb + (size_t)r * Tq + sT * 64 + c4);
            Ps[c4 + 0][r] = vp.x; Ps[c4 + 1][r] = vp.y;
            Ps[c4 + 2][r] = vp.z; Ps[c4 + 3][r] = vp.w;
            float4 vv = *(const float4*)(vb + (size_t)(sT * 64 + r) * Dq + c4);
            *(float4*)(&Vs[r][c4]) = vv;
        }
        __syncthreads();

#pragma unroll
        for (int kk = 0; kk < 64; kk++) {
            float rp[4], rv[4];
#pragma unroll
            for (int i = 0; i < 4; i++) rp[i] = Ps[kk][tr + i];
#pragma unroll
            for (int j = 0; j < 4; j++) rv[j] = Vs[kk][tc + j];
#pragma unroll
            for (int i = 0; i < 4; i++)
#pragma unroll
                for (int j = 0; j < 4; j++)
                    acc[i][j] = fmaf(rp[i], rv[j], acc[i][j]);
        }
        __syncthreads();
    }

#pragma unroll
    for (int i = 0; i < 4; i++) {
        int t = tT * 64 + tr + i;
#pragma unroll
        for (int j = 0; j < 4; j++) {
            g_ctx[(size_t)(b * Tq + t) * Cq + h * 64 + tc + j] = acc[i][j];
        }
    }
}

// ---------------------------------------------------------------------------
// Launch
// ---------------------------------------------------------------------------
extern "C" void kernel_launch(void* const* d_in, const int* in_sizes, int n_in,
                              void* d_out, int out_size) {
    const float* x     = (const float*)d_in[0];
    const float* Wq    = (const float*)d_in[1];
    const float* Wk    = (const float*)d_in[2];
    const float* Wv    = (const float*)d_in[3];
    const float* Wproj = (const float*)d_in[4];
    const float* bproj = (const float*)d_in[5];

    float* out = (float*)d_out;                       // [B,T,C]
    float* wei = out + (size_t)Bq * Tq * Cq;          // [B,H,T,T]

    float *pq, *pk, *pv, *pctx, *pwq, *pwk, *pwv, *pwpT;
    cudaGetSymbolAddress((void**)&pq,   g_q);
    cudaGetSymbolAddress((void**)&pk,   g_k);
    cudaGetSymbolAddress((void**)&pv,   g_v);
    cudaGetSymbolAddress((void**)&pctx, g_ctx);
    cudaGetSymbolAddress((void**)&pwq,  g_wq);
    cudaGetSymbolAddress((void**)&pwk,  g_wk);
    cudaGetSymbolAddress((void**)&pwv,  g_wv);
    cudaGetSymbolAddress((void**)&pwpT, g_wpT);

    // 1) repack weights
    repack_qkv_kernel<<<4096, 256>>>(Wq, pwq);
    repack_qkv_kernel<<<4096, 256>>>(Wk, pwk);
    repack_qkv_kernel<<<4096, 256>>>(Wv, pwv);
    repack_projT_kernel<<<4096, 256>>>(Wproj, pwpT);

    // 2) Q/K/V projections (scatter into [B,H,T,D])
    dim3 gproj(Cq / 128, Mq / 128);
    sgemm128<<<gproj, 256>>>(x, pwq, pq, Cq, Cq, 1, nullptr);
    sgemm128<<<gproj, 256>>>(x, pwk, pk, Cq, Cq, 1, nullptr);
    sgemm128<<<gproj, 256>>>(x, pwv, pv, Cq, Cq, 1, nullptr);

    // 3) scores (causal half only)
    dim3 gsc(Tq / 64, Tq / 64, BHq);
    scores_kernel<<<gsc, 256>>>(wei);

    // 4) softmax in place (writes zeros above diagonal)
    softmax_kernel<<<BHq * Tq, 256>>>(wei);

    // 5) ctx = P @ V  -> [B,T,C]
    dim3 gctx(Tq / 64, BHq);
    ctx_kernel<<<gctx, 256>>>(wei);

    // 6) out = ctx @ Wproj^T + b
    dim3 gout(Cq / 128, Mq / 128);
    sgemm128<<<gout, 256>>>(pctx, pwpT, out, Cq, Cq, 0, bproj);
}